// round 12
// baseline (speedup 1.0000x reference)
#include <cuda_runtime.h>

#define DM   64
#define DI   128
#define DS   16
#define DR   32
#define LSEQ 4096
#define NPOS 8192
#define PPB  32
#define NTH  256
#define NCTA (NPOS/PPB)
#define OUT_CONV (2*DM*LSEQ)   /* 524288 floats: [2,64,64,64] conv3 output */

// ---------------- device scratch (allocation-free) ----------------
__device__ float g_rgb[NPOS*DM];
__device__ float g_dte[NPOS*DM];
__device__ float g_x  [NPOS*DM];          // rmsnormed x (residual source)
__device__ float g_out[NPOS*DM];          // block output
__device__ float g_xcz[NPOS*2*DI];        // in_proj output [pos][256]
__device__ float g_h  [(size_t)NPOS*DI*DS]; // 67 MB, L2-resident
__device__ float g_ipwT[DM*2*DI];         // [k][o]
__device__ float g_xpwT[DI*(DR+2*DS)];    // [k][o] 128x64
__device__ float g_dtwT[DR*DI];           // [r][d]
__device__ float g_opwT[DI*DM];           // [d][o]
__device__ float g_Ad  [DI*DS];           // A = -exp(A_log), [d][s]
__device__ float g_c3wT[DM*DM];           // [c][o]

// ---------------- FFMA-pipe exp (no MUFU) ----------------
__device__ __forceinline__ float fexp(float x){
    float t = x * 1.4426950408889634f;
    t = fminf(fmaxf(t, -125.0f), 125.0f);
    float tn = __fadd_rn(t, 12582912.0f);          // round-to-int trick
    int   e  = __float_as_int(tn) - 0x4B400000;
    float n  = __fsub_rn(tn, 12582912.0f);
    float f  = t - n;                               // f in [-0.5, 0.5]
    float p =        1.3333558146e-3f;
    p = fmaf(p, f,   9.6181291076e-3f);
    p = fmaf(p, f,   5.5504108665e-2f);
    p = fmaf(p, f,   2.4022650696e-1f);
    p = fmaf(p, f,   6.9314718056e-1f);
    p = fmaf(p, f,   1.0f);
    return p * __int_as_float((e + 127) << 23);
}
__device__ __forceinline__ float fsig(float x){
    return __fdividef(1.0f, 1.0f + fexp(-x));
}
__device__ __forceinline__ float fsoftplus(float x){
    return fmaxf(x, 0.0f) + __logf(1.0f + fexp(-fabsf(x)));
}

// ---------------- prologue: weight transposes + A ----------------
__global__ void kPrep(const float* __restrict__ ipw, const float* __restrict__ xpw,
                      const float* __restrict__ dtw, const float* __restrict__ opw,
                      const float* __restrict__ alog, const float* __restrict__ c3w){
    int t = blockIdx.x*blockDim.x + threadIdx.x;
    int n = gridDim.x*blockDim.x;
    for (int e = t; e < DM*2*DI; e += n){ int o = e/DM,  k = e%DM;  g_ipwT[k*(2*DI)+o] = ipw[e]; }
    for (int e = t; e < 64*DI;   e += n){ int o = e/DI,  k = e%DI;  g_xpwT[k*64+o]     = xpw[e]; }
    for (int e = t; e < DI*DR;   e += n){ int d = e/DR,  r = e%DR;  g_dtwT[r*DI+d]     = dtw[e]; }
    for (int e = t; e < DM*DI;   e += n){ int o = e/DI,  d = e%DI;  g_opwT[d*DM+o]     = opw[e]; }
    for (int e = t; e < DI*DS;   e += n){ g_Ad[e] = -expf(alog[e]); }
    for (int e = t; e < 64*64;   e += n){ int o = e/64,  c = e%64;  g_c3wT[c*64+o]     = c3w[e]; }
}

// ---------------- prologue: 1x1 conv NCHW -> [pos][c] ----------------
__global__ __launch_bounds__(NTH) void kConvIn(const float* __restrict__ feat,
                                               const float* __restrict__ w,
                                               const float* __restrict__ bias, int tgt){
    __shared__ float fs[64*33];
    float* dst = tgt ? g_dte : g_rgb;
    int t = threadIdx.x;
    int pos0 = blockIdx.x * PPB;
    int b = pos0 >> 12, hw0 = pos0 & 4095;
    const float* fb = feat + (size_t)b*64*4096 + hw0;
    #pragma unroll
    for (int i = 0; i < 8; i++){
        int e = t + 256*i; int p = e & 31, c = e >> 5;
        fs[c*33+p] = fb[(size_t)c*4096 + p];
    }
    __syncthreads();
    int o = t & 63, pg = t >> 6;
    float acc[8];
    #pragma unroll
    for (int i = 0; i < 8; i++) acc[i] = 0.f;
    const float* wr = w + o*64;
    #pragma unroll 8
    for (int c = 0; c < 64; c++){
        float wv = __ldg(wr + c);
        #pragma unroll
        for (int i = 0; i < 8; i++) acc[i] = fmaf(wv, fs[c*33 + pg*8 + i], acc[i]);
    }
    float bv = __ldg(bias + o);
    #pragma unroll
    for (int i = 0; i < 8; i++) dst[(size_t)(pos0 + pg*8 + i)*64 + o] = acc[i] + bv;
}

// ---------------- kernel A: combine + rmsnorm + in_proj ----------------
#define A_SMEM ((64*256 + 32*65 + 32)*4)
__global__ __launch_bounds__(NTH, 2) void kA(int useDte, int addPrev,
                                             const float* __restrict__ norm_w){
    extern __shared__ float sm[];
    float* wsm   = sm;                  // 64*256
    float* xs    = sm + 64*256;         // 32*65 (padded)
    float* scale = xs + 32*65;          // 32
    const float* base = useDte ? g_dte : g_rgb;
    int t = threadIdx.x;
    int pos0 = blockIdx.x * PPB;

    #pragma unroll
    for (int i = 0; i < 64; i++) wsm[t + 256*i] = g_ipwT[t + 256*i];
    #pragma unroll
    for (int i = 0; i < 8; i++){
        int e = t + 256*i; int c = e & 63, p = e >> 6;
        size_t gi = (size_t)(pos0 + p)*64 + c;
        float v = base[gi];
        if (addPrev) v += g_out[gi];
        xs[p*65 + c] = v;
    }
    __syncthreads();
    {   // rmsnorm: 8 threads per position
        int p = t >> 3, lane8 = t & 7;
        float s = 0.f;
        #pragma unroll
        for (int j = 0; j < 8; j++){ float v = xs[p*65 + lane8 + 8*j]; s = fmaf(v, v, s); }
        #pragma unroll
        for (int m = 4; m >= 1; m >>= 1) s += __shfl_xor_sync(0xffffffffu, s, m);
        if (lane8 == 0) scale[p] = rsqrtf(s*(1.f/64.f) + 1e-5f);
    }
    __syncthreads();
    #pragma unroll
    for (int i = 0; i < 8; i++){
        int e = t + 256*i; int c = e & 63, p = e >> 6;
        float v = xs[p*65 + c] * scale[p] * __ldg(norm_w + c);
        xs[p*65 + c] = v;
        g_x[(size_t)(pos0 + p)*64 + c] = v;
    }
    __syncthreads();
    // matvec 64 -> 256 : 4 outputs x 8 positions per thread
    int ob = t & 63, pg = t >> 6;
    float acc[4][8];
    #pragma unroll
    for (int j = 0; j < 4; j++)
        #pragma unroll
        for (int i = 0; i < 8; i++) acc[j][i] = 0.f;
    #pragma unroll 4
    for (int k = 0; k < 64; k++){
        float w0 = wsm[k*256 + ob      ];
        float w1 = wsm[k*256 + ob +  64];
        float w2 = wsm[k*256 + ob + 128];
        float w3 = wsm[k*256 + ob + 192];
        #pragma unroll
        for (int i = 0; i < 8; i++){
            float xv = xs[(pg*8 + i)*65 + k];
            acc[0][i] = fmaf(w0, xv, acc[0][i]);
            acc[1][i] = fmaf(w1, xv, acc[1][i]);
            acc[2][i] = fmaf(w2, xv, acc[2][i]);
            acc[3][i] = fmaf(w3, xv, acc[3][i]);
        }
    }
    #pragma unroll
    for (int j = 0; j < 4; j++)
        #pragma unroll
        for (int i = 0; i < 8; i++)
            g_xcz[(size_t)(pos0 + pg*8 + i)*256 + ob + 64*j] = acc[j][i];
}

// ---------------- kernel B: conv1d/ssm/out_proj (+conv3 on last) ----------------
#define B_SMEM ((34*128 + 32*128 + 32*64 + 32*128 + 32*128 + 32*128 + 32*65)*4)
__global__ __launch_bounds__(NTH, 2) void kB(const float* __restrict__ c1dw,
                                             const float* __restrict__ c1db,
                                             const float* __restrict__ dtb,
                                             const float* __restrict__ Dpp,
                                             const float* __restrict__ c3b,
                                             int firstH, int lastBlk,
                                             float* dout, float* hExt){
    extern __shared__ float sm[];
    float* xcs  = sm;                 // 34*128
    float* xcv  = xcs  + 34*128;      // 32*128
    float* dbc  = xcv  + 32*128;      // 32*64
    float* dels = dbc  + 32*64;       // 32*128
    float* ysm  = dels + 32*128;      // 32*128
    float* dtw  = ysm  + 32*128;      // 32*128
    float* obuf = dtw  + 32*128;      // 32*65
    int t = threadIdx.x;
    int pos0 = blockIdx.x * PPB;
    int b = pos0 >> 12, l0 = pos0 & 4095;
    float* hdst = hExt ? hExt : g_h;

    #pragma unroll
    for (int i = 0; i < 16; i++) dtw[t + 256*i] = g_dtwT[t + 256*i];
    // load xc (pre-conv) rows for positions l0-1 .. l0+32 with batch-boundary zero pad
    for (int e = t; e < 34*128; e += 256){
        int r = e >> 7, d = e & 127;
        int lsrc = l0 - 1 + r;
        float v = 0.f;
        if (lsrc >= 0 && lsrc < 4096) v = g_xcz[(size_t)(b*4096 + lsrc)*256 + d];
        xcs[e] = v;
    }
    __syncthreads();
    // depthwise conv1d + silu
    {
        int d = t & 127;
        float w0 = __ldg(c1dw + d*3), w1 = __ldg(c1dw + d*3 + 1), w2 = __ldg(c1dw + d*3 + 2);
        float bv = __ldg(c1db + d);
        #pragma unroll
        for (int i = 0; i < 16; i++){
            int p = (t >> 7) + 2*i;
            float v = bv;
            v = fmaf(w0, xcs[ p   *128 + d], v);
            v = fmaf(w1, xcs[(p+1)*128 + d], v);
            v = fmaf(w2, xcs[(p+2)*128 + d], v);
            xcv[p*128 + d] = v * fsig(v);
        }
    }
    __syncthreads();
    // x_proj: 128 -> 64
    {
        int o = t & 63, pg = t >> 6;
        float acc[8];
        #pragma unroll
        for (int i = 0; i < 8; i++) acc[i] = 0.f;
        #pragma unroll 8
        for (int k = 0; k < 128; k++){
            float w = __ldg(&g_xpwT[k*64 + o]);
            #pragma unroll
            for (int i = 0; i < 8; i++) acc[i] = fmaf(w, xcv[(pg*8 + i)*128 + k], acc[i]);
        }
        #pragma unroll
        for (int i = 0; i < 8; i++) dbc[(pg*8 + i)*64 + o] = acc[i];
    }
    __syncthreads();
    // dt_proj + softplus: 32 -> 128
    {
        int dl = t & 31, pg = t >> 5;   // d = dl + 32j, p = pg + 8i
        float acc[4][4];
        #pragma unroll
        for (int j = 0; j < 4; j++)
            #pragma unroll
            for (int i = 0; i < 4; i++) acc[j][i] = 0.f;
        #pragma unroll
        for (int r = 0; r < 32; r++){
            float w0 = dtw[r*128 + dl     ];
            float w1 = dtw[r*128 + dl + 32];
            float w2 = dtw[r*128 + dl + 64];
            float w3 = dtw[r*128 + dl + 96];
            #pragma unroll
            for (int i = 0; i < 4; i++){
                float xv = dbc[(pg + 8*i)*64 + r];
                acc[0][i] = fmaf(w0, xv, acc[0][i]);
                acc[1][i] = fmaf(w1, xv, acc[1][i]);
                acc[2][i] = fmaf(w2, xv, acc[2][i]);
                acc[3][i] = fmaf(w3, xv, acc[3][i]);
            }
        }
        #pragma unroll
        for (int j = 0; j < 4; j++){
            float bv = __ldg(dtb + dl + 32*j);
            #pragma unroll
            for (int i = 0; i < 4; i++)
                dels[(pg + 8*i)*128 + dl + 32*j] = fsoftplus(acc[j][i] + bv);
        }
    }
    __syncthreads();
    // SSM h-update + y + gate
    {
        int d = t & 127;
        float al[16];
        {
            const float4* Ar = reinterpret_cast<const float4*>(g_Ad + d*16);
            float4 a0 = __ldg(Ar), a1 = __ldg(Ar+1), a2 = __ldg(Ar+2), a3 = __ldg(Ar+3);
            al[0]=a0.x; al[1]=a0.y; al[2]=a0.z; al[3]=a0.w;
            al[4]=a1.x; al[5]=a1.y; al[6]=a1.z; al[7]=a1.w;
            al[8]=a2.x; al[9]=a2.y; al[10]=a2.z; al[11]=a2.w;
            al[12]=a3.x; al[13]=a3.y; al[14]=a3.z; al[15]=a3.w;
        }
        float dpv = __ldg(Dpp + d);
        #pragma unroll 1
        for (int i = 0; i < 16; i++){
            int p = (t >> 7) + 2*i;
            size_t pos = (size_t)(pos0 + p);
            float delta = dels[p*128 + d];
            float xc = xcv[p*128 + d];
            float dx = delta * xc;
            const float* bm = dbc + p*64 + 32;
            const float* cm = dbc + p*64 + 48;
            size_t hoff = pos*2048 + (size_t)d*16;
            float hl[16];
            if (firstH){
                #pragma unroll
                for (int s = 0; s < 16; s++) hl[s] = 0.f;
            } else {
                const float4* hp = reinterpret_cast<const float4*>(g_h + hoff);
                float4 h0 = hp[0], h1 = hp[1], h2 = hp[2], h3 = hp[3];
                hl[0]=h0.x; hl[1]=h0.y; hl[2]=h0.z; hl[3]=h0.w;
                hl[4]=h1.x; hl[5]=h1.y; hl[6]=h1.z; hl[7]=h1.w;
                hl[8]=h2.x; hl[9]=h2.y; hl[10]=h2.z; hl[11]=h2.w;
                hl[12]=h3.x; hl[13]=h3.y; hl[14]=h3.z; hl[15]=h3.w;
            }
            float y = 0.f;
            #pragma unroll
            for (int s = 0; s < 16; s++){
                float hn = fmaf(fexp(delta * al[s]), hl[s], dx * bm[s]);
                hl[s] = hn;
                y = fmaf(hn, cm[s], y);
            }
            float4* op = reinterpret_cast<float4*>(hdst + hoff);
            op[0] = make_float4(hl[0],  hl[1],  hl[2],  hl[3]);
            op[1] = make_float4(hl[4],  hl[5],  hl[6],  hl[7]);
            op[2] = make_float4(hl[8],  hl[9],  hl[10], hl[11]);
            op[3] = make_float4(hl[12], hl[13], hl[14], hl[15]);
            float z = __ldg((const float*)g_xcz + pos*256 + 128 + d);
            ysm[p*128 + d] = fmaf(dpv, xc, y) * (z * fsig(z));
        }
    }
    __syncthreads();
    // out_proj 128 -> 64 (+ residual) [+ fused conv3 on last block]
    {
        int o = t & 63, pg = t >> 6;
        float acc[8];
        #pragma unroll
        for (int i = 0; i < 8; i++) acc[i] = 0.f;
        #pragma unroll 8
        for (int d = 0; d < 128; d++){
            float w = __ldg(&g_opwT[d*64 + o]);
            #pragma unroll
            for (int i = 0; i < 8; i++) acc[i] = fmaf(w, ysm[(pg*8 + i)*128 + d], acc[i]);
        }
        #pragma unroll
        for (int i = 0; i < 8; i++){
            int p = pg*8 + i;
            size_t pos = (size_t)(pos0 + p);
            float res = acc[i] + __ldg((const float*)g_x + pos*64 + o);
            if (!lastBlk) g_out[pos*64 + o] = res;
            else          obuf[p*65 + o]   = res;
        }
    }
    if (lastBlk){
        __syncthreads();
        int pl = t & 31, og = t >> 5;   // o2 = og + 8j
        float acc2[8];
        #pragma unroll
        for (int j = 0; j < 8; j++) acc2[j] = 0.f;
        #pragma unroll 4
        for (int c = 0; c < 64; c++){
            float xv = obuf[pl*65 + c];
            #pragma unroll
            for (int j = 0; j < 8; j++)
                acc2[j] = fmaf(__ldg(&g_c3wT[c*64 + og + 8*j]), xv, acc2[j]);
        }
        #pragma unroll
        for (int j = 0; j < 8; j++){
            int o2 = og + 8*j;
            dout[(size_t)b*262144 + (size_t)o2*4096 + l0 + pl] = acc2[j] + __ldg(c3b + o2);
        }
    }
}

extern "C" void kernel_launch(void* const* d_in, const int* in_sizes, int n_in,
                              void* d_out, int out_size){
    (void)in_sizes; (void)n_in;
    const float* rgb  = (const float*)d_in[0];
    const float* dte  = (const float*)d_in[1];
    const float* c1w  = (const float*)d_in[2];
    const float* c1b  = (const float*)d_in[3];
    const float* c2w  = (const float*)d_in[4];
    const float* c2b  = (const float*)d_in[5];
    const float* c3w  = (const float*)d_in[6];
    const float* c3b  = (const float*)d_in[7];
    const float* nw   = (const float*)d_in[8];
    const float* ipw  = (const float*)d_in[9];
    const float* cdw  = (const float*)d_in[10];
    const float* cdb  = (const float*)d_in[11];
    const float* xpw  = (const float*)d_in[12];
    const float* dtw  = (const float*)d_in[13];
    const float* dtb  = (const float*)d_in[14];
    const float* alog = (const float*)d_in[15];
    const float* Dp   = (const float*)d_in[16];
    const float* opw  = (const float*)d_in[17];
    float* out = (float*)d_out;

    cudaFuncSetAttribute(kA, cudaFuncAttributeMaxDynamicSharedMemorySize, A_SMEM);
    cudaFuncSetAttribute(kB, cudaFuncAttributeMaxDynamicSharedMemorySize, B_SMEM);

    kPrep<<<64, 256>>>(ipw, xpw, dtw, opw, alog, c3w);
    kConvIn<<<NCTA, NTH>>>(rgb, c1w, c1b, 0);
    kConvIn<<<NCTA, NTH>>>(dte, c2w, c2b, 1);

    // second output (final h) appended after conv output, if the harness expects it
    float* hExt = (out_size >= OUT_CONV + NPOS*DI*DS) ? (out + OUT_CONV) : nullptr;

    for (int k = 0; k < 6; k++){
        kA<<<NCTA, NTH, A_SMEM>>>(k & 1, k > 0, nw);
        int last = (k == 5);
        kB<<<NCTA, NTH, B_SMEM>>>(cdw, cdb, dtb, Dp, c3b,
                                  (k == 0) ? 1 : 0, last, out,
                                  last ? hExt : nullptr);
    }
}

// round 13
// speedup vs baseline: 1.7006x; 1.7006x over previous
#include <cuda_runtime.h>

#define DM   64
#define DI   128
#define DS   16
#define DR   32
#define LSEQ 4096
#define NPOS 8192
#define PPB  32
#define NTH  256
#define NCTA (NPOS/PPB)
#define OUT_CONV (2*DM*LSEQ)   /* 524288 floats: [2,64,64,64] conv3 output */

// ---------------- device scratch (allocation-free) ----------------
__device__ float g_rgb[NPOS*DM];
__device__ float g_dte[NPOS*DM];
__device__ float g_out[NPOS*DM];            // block output (residual stream)
__device__ float g_h  [(size_t)NPOS*DI*DS]; // 67 MB, L2-resident
__device__ float g_ipwT[DM*2*DI];           // [k][o] 64x256
__device__ float g_xpwT[DI*64];             // [k][o] 128x64
__device__ float g_dtwT[DR*DI];             // [r][d] 32x128
__device__ float g_opwT[DI*DM];             // [d][o] 128x64
__device__ float g_Ad  [DI*DS];             // A = -exp(A_log), [d][s]
__device__ float g_c3wT[DM*DM];             // [c][o]

__device__ __forceinline__ float fsilu(float x){
    return __fdividef(x, 1.0f + __expf(-x));
}
__device__ __forceinline__ float fsoftplus(float x){
    return fmaxf(x, 0.0f) + __logf(1.0f + __expf(-fabsf(x)));
}

// ---------------- prologue: weight transposes + A ----------------
__global__ void kPrep(const float* __restrict__ ipw, const float* __restrict__ xpw,
                      const float* __restrict__ dtw, const float* __restrict__ opw,
                      const float* __restrict__ alog, const float* __restrict__ c3w){
    int t = blockIdx.x*blockDim.x + threadIdx.x;
    int n = gridDim.x*blockDim.x;
    for (int e = t; e < DM*2*DI; e += n){ int o = e/DM,  k = e%DM;  g_ipwT[k*(2*DI)+o] = ipw[e]; }
    for (int e = t; e < 64*DI;   e += n){ int o = e/DI,  k = e%DI;  g_xpwT[k*64+o]     = xpw[e]; }
    for (int e = t; e < DI*DR;   e += n){ int d = e/DR,  r = e%DR;  g_dtwT[r*DI+d]     = dtw[e]; }
    for (int e = t; e < DM*DI;   e += n){ int o = e/DI,  d = e%DI;  g_opwT[d*DM+o]     = opw[e]; }
    for (int e = t; e < DI*DS;   e += n){ g_Ad[e] = -expf(alog[e]); }
    for (int e = t; e < 64*64;   e += n){ int o = e/64,  c = e%64;  g_c3wT[c*64+o]     = c3w[e]; }
}

// ---------------- prologue: 1x1 conv NCHW -> [pos][c] ----------------
__global__ __launch_bounds__(NTH) void kConvIn(const float* __restrict__ feat,
                                               const float* __restrict__ w,
                                               const float* __restrict__ bias, int tgt){
    __shared__ float fs[64*33];
    float* dst = tgt ? g_dte : g_rgb;
    int t = threadIdx.x;
    int pos0 = blockIdx.x * PPB;
    int b = pos0 >> 12, hw0 = pos0 & 4095;
    const float* fb = feat + (size_t)b*64*4096 + hw0;
    #pragma unroll
    for (int i = 0; i < 8; i++){
        int e = t + 256*i; int p = e & 31, c = e >> 5;
        fs[c*33+p] = fb[(size_t)c*4096 + p];
    }
    __syncthreads();
    int o = t & 63, pg = t >> 6;
    float acc[8];
    #pragma unroll
    for (int i = 0; i < 8; i++) acc[i] = 0.f;
    const float* wr = w + o*64;
    #pragma unroll 8
    for (int c = 0; c < 64; c++){
        float wv = __ldg(wr + c);
        #pragma unroll
        for (int i = 0; i < 8; i++) acc[i] = fmaf(wv, fs[c*33 + pg*8 + i], acc[i]);
    }
    float bv = __ldg(bias + o);
    #pragma unroll
    for (int i = 0; i < 8; i++) dst[(size_t)(pos0 + pg*8 + i)*64 + o] = acc[i] + bv;
}

// ---------------- fused per-block kernel ----------------
// 32 positions/CTA + 2-row halo recompute (rows 0..33 <-> l0-1..l0+32, rows 34/35 pad)
// smem floats: xs 36*65 | scl 40 | bigA 36*128 (xc -> dels) | bigB 36*128 (z -> ygated)
//              xcv 32*128 (-> obuf) | dbc 32*64
#define F_SMEM ((36*65 + 40 + 36*128 + 36*128 + 32*128 + 32*64)*4)

__global__ __launch_bounds__(NTH, 2) void kFused(int useDte, int addPrev,
                                                 const float* __restrict__ norm_w,
                                                 const float* __restrict__ c1dw,
                                                 const float* __restrict__ c1db,
                                                 const float* __restrict__ dtb,
                                                 const float* __restrict__ Dpp,
                                                 const float* __restrict__ c3b,
                                                 int firstH, int lastBlk,
                                                 float* dout, float* hExt){
    extern __shared__ float sm[];
    float* xs   = sm;                 // 36*65 normed x (halo rows)
    float* scl  = xs   + 36*65;      // 40
    float* bigA = scl  + 40;         // 36*128  xc, later dels
    float* bigB = bigA + 36*128;     // 36*128  z,  later gated y
    float* xcv  = bigB + 36*128;     // 32*128  conv+silu, later obuf(32*65)
    float* dbc  = xcv  + 32*128;     // 32*64

    int t = threadIdx.x;
    int pos0 = blockIdx.x * PPB;
    int b = pos0 >> 12, l0 = pos0 & 4095;
    const float* base = useDte ? g_dte : g_rgb;
    float* hdst = hExt ? hExt : g_h;

    // ---- load x rows (halo, zero-padded) ----
    #pragma unroll
    for (int i = 0; i < 9; i++){
        int e = t + 256*i;           // e < 2304 = 36*64
        int r = e >> 6, c = e & 63;
        int lsrc = l0 - 1 + r;
        float v = 0.f;
        if (r < 34 && lsrc >= 0 && lsrc < 4096){
            size_t gi = (size_t)(b*4096 + lsrc)*64 + c;
            v = base[gi];
            if (addPrev) v += g_out[gi];
        }
        xs[r*65 + c] = v;
    }
    __syncthreads();
    // ---- rmsnorm scales (8 threads per row) ----
    for (int r = t >> 3; r < 36; r += 32){
        int lane8 = t & 7;
        float s = 0.f;
        #pragma unroll
        for (int j = 0; j < 8; j++){ float v = xs[r*65 + lane8 + 8*j]; s = fmaf(v, v, s); }
        #pragma unroll
        for (int m = 4; m >= 1; m >>= 1) s += __shfl_xor_sync(0xffffffffu, s, m);
        if (lane8 == 0) scl[r] = rsqrtf(s*(1.f/64.f) + 1e-5f);
    }
    __syncthreads();
    #pragma unroll
    for (int i = 0; i < 9; i++){
        int e = t + 256*i;
        int r = e >> 6, c = e & 63;
        xs[r*65 + c] = xs[r*65 + c] * scl[r] * __ldg(norm_w + c);
    }
    __syncthreads();

    // ---- in_proj 64 -> 256 over 36 rows (xc -> bigA, z -> bigB) ----
    {
        int ob = t & 63, pg = t >> 6;       // rows pg*9 .. pg*9+8
        float acc[4][9];
        #pragma unroll
        for (int j = 0; j < 4; j++)
            #pragma unroll
            for (int i = 0; i < 9; i++) acc[j][i] = 0.f;
        #pragma unroll 4
        for (int k = 0; k < 64; k++){
            float w0 = __ldg(&g_ipwT[k*256 + ob      ]);
            float w1 = __ldg(&g_ipwT[k*256 + ob +  64]);
            float w2 = __ldg(&g_ipwT[k*256 + ob + 128]);
            float w3 = __ldg(&g_ipwT[k*256 + ob + 192]);
            #pragma unroll
            for (int i = 0; i < 9; i++){
                float xv = xs[(pg*9 + i)*65 + k];
                acc[0][i] = fmaf(w0, xv, acc[0][i]);
                acc[1][i] = fmaf(w1, xv, acc[1][i]);
                acc[2][i] = fmaf(w2, xv, acc[2][i]);
                acc[3][i] = fmaf(w3, xv, acc[3][i]);
            }
        }
        #pragma unroll
        for (int i = 0; i < 9; i++){
            int r = pg*9 + i;
            bigA[r*128 + ob     ] = acc[0][i];
            bigA[r*128 + ob + 64] = acc[1][i];
            bigB[r*128 + ob     ] = acc[2][i];
            bigB[r*128 + ob + 64] = acc[3][i];
        }
    }
    __syncthreads();

    // ---- depthwise conv1d + silu -> xcv ----
    {
        int d = t & 127;
        float w0 = __ldg(c1dw + d*3), w1 = __ldg(c1dw + d*3 + 1), w2 = __ldg(c1dw + d*3 + 2);
        float bv = __ldg(c1db + d);
        #pragma unroll
        for (int i = 0; i < 16; i++){
            int p = (t >> 7) + 2*i;
            float v = bv;
            v = fmaf(w0, bigA[ p   *128 + d], v);
            v = fmaf(w1, bigA[(p+1)*128 + d], v);
            v = fmaf(w2, bigA[(p+2)*128 + d], v);
            xcv[p*128 + d] = fsilu(v);
        }
    }
    __syncthreads();

    // ---- x_proj 128 -> 64 ----
    {
        int o = t & 63, pg = t >> 6;
        float acc[8];
        #pragma unroll
        for (int i = 0; i < 8; i++) acc[i] = 0.f;
        #pragma unroll 8
        for (int k = 0; k < 128; k++){
            float w = __ldg(&g_xpwT[k*64 + o]);
            #pragma unroll
            for (int i = 0; i < 8; i++) acc[i] = fmaf(w, xcv[(pg*8 + i)*128 + k], acc[i]);
        }
        #pragma unroll
        for (int i = 0; i < 8; i++) dbc[(pg*8 + i)*64 + o] = acc[i];
    }
    __syncthreads();

    // ---- dt_proj 32 -> 128 + softplus -> dels (reuse bigA) ----
    {
        int dl = t & 31, pg5 = t >> 5;      // p = pg5 + 8i, d = dl + 32j
        float acc[4][4];
        #pragma unroll
        for (int j = 0; j < 4; j++)
            #pragma unroll
            for (int i = 0; i < 4; i++) acc[j][i] = 0.f;
        #pragma unroll 8
        for (int r = 0; r < 32; r++){
            float w0 = __ldg(&g_dtwT[r*128 + dl     ]);
            float w1 = __ldg(&g_dtwT[r*128 + dl + 32]);
            float w2 = __ldg(&g_dtwT[r*128 + dl + 64]);
            float w3 = __ldg(&g_dtwT[r*128 + dl + 96]);
            #pragma unroll
            for (int i = 0; i < 4; i++){
                float xv = dbc[(pg5 + 8*i)*64 + r];
                acc[0][i] = fmaf(w0, xv, acc[0][i]);
                acc[1][i] = fmaf(w1, xv, acc[1][i]);
                acc[2][i] = fmaf(w2, xv, acc[2][i]);
                acc[3][i] = fmaf(w3, xv, acc[3][i]);
            }
        }
        #pragma unroll
        for (int j = 0; j < 4; j++){
            float bv = __ldg(dtb + dl + 32*j);
            #pragma unroll
            for (int i = 0; i < 4; i++)
                bigA[(pg5 + 8*i)*128 + dl + 32*j] = fsoftplus(acc[j][i] + bv);
        }
    }
    __syncthreads();

    // ---- SSM h-update + y + gate (h prefetch pipeline) ----
    {
        int d = t & 127;
        int p0 = t >> 7;                    // tasks p = p0 + 2i
        float al[16];
        {
            const float4* Ar = reinterpret_cast<const float4*>(g_Ad + d*16);
            float4 a0 = __ldg(Ar), a1 = __ldg(Ar+1), a2 = __ldg(Ar+2), a3 = __ldg(Ar+3);
            al[0]=a0.x; al[1]=a0.y; al[2]=a0.z;  al[3]=a0.w;
            al[4]=a1.x; al[5]=a1.y; al[6]=a1.z;  al[7]=a1.w;
            al[8]=a2.x; al[9]=a2.y; al[10]=a2.z; al[11]=a2.w;
            al[12]=a3.x; al[13]=a3.y; al[14]=a3.z; al[15]=a3.w;
        }
        float dpv = __ldg(Dpp + d);
        size_t hbase = ((size_t)(pos0 + p0))*2048 + (size_t)d*16;
        const float4* hp = reinterpret_cast<const float4*>(g_h + hbase);
        float4 c0, c1, c2, c3;
        if (!firstH){ c0 = __ldg(hp); c1 = __ldg(hp+1); c2 = __ldg(hp+2); c3 = __ldg(hp+3); }
        #pragma unroll 1
        for (int i = 0; i < 16; i++){
            int p = p0 + 2*i;
            float hl[16];
            if (firstH){
                #pragma unroll
                for (int s = 0; s < 16; s++) hl[s] = 0.f;
            } else {
                hl[0]=c0.x;  hl[1]=c0.y;  hl[2]=c0.z;  hl[3]=c0.w;
                hl[4]=c1.x;  hl[5]=c1.y;  hl[6]=c1.z;  hl[7]=c1.w;
                hl[8]=c2.x;  hl[9]=c2.y;  hl[10]=c2.z; hl[11]=c2.w;
                hl[12]=c3.x; hl[13]=c3.y; hl[14]=c3.z; hl[15]=c3.w;
                if (i < 15){                // prefetch next task's h
                    const float4* hn = hp + (size_t)1024*(i+1);
                    c0 = __ldg(hn); c1 = __ldg(hn+1); c2 = __ldg(hn+2); c3 = __ldg(hn+3);
                }
            }
            float delta = bigA[p*128 + d];
            float xc    = xcv [p*128 + d];
            float dx = delta * xc;
            const float* bm = dbc + p*64 + 32;
            const float* cm = bm + 16;
            float y = 0.f;
            #pragma unroll
            for (int s = 0; s < 16; s++){
                float hn = fmaf(__expf(delta * al[s]), hl[s], dx * bm[s]);
                hl[s] = hn;
                y = fmaf(hn, cm[s], y);
            }
            float4* op = reinterpret_cast<float4*>(hdst + hbase + (size_t)4096*i);
            op[0] = make_float4(hl[0],  hl[1],  hl[2],  hl[3]);
            op[1] = make_float4(hl[4],  hl[5],  hl[6],  hl[7]);
            op[2] = make_float4(hl[8],  hl[9],  hl[10], hl[11]);
            op[3] = make_float4(hl[12], hl[13], hl[14], hl[15]);
            int zi = (p+1)*128 + d;
            float z = bigB[zi];
            bigB[zi] = fmaf(dpv, xc, y) * fsilu(z);    // gated y, in place
        }
    }
    __syncthreads();

    // ---- out_proj 128 -> 64 + residual ----
    float* obuf = xcv;   // 32*65, xcv dead
    {
        int o = t & 63, pg = t >> 6;
        float acc[8];
        #pragma unroll
        for (int i = 0; i < 8; i++) acc[i] = 0.f;
        #pragma unroll 8
        for (int dd = 0; dd < 128; dd++){
            float w = __ldg(&g_opwT[dd*64 + o]);
            #pragma unroll
            for (int i = 0; i < 8; i++)
                acc[i] = fmaf(w, bigB[(pg*8 + i + 1)*128 + dd], acc[i]);
        }
        #pragma unroll
        for (int i = 0; i < 8; i++){
            int p = pg*8 + i;
            float res = acc[i] + xs[(p+1)*65 + o];
            if (!lastBlk) g_out[(size_t)(pos0 + p)*64 + o] = res;
            else          obuf[p*65 + o] = res;
        }
    }
    // ---- fused conv3 on last block ----
    if (lastBlk){
        __syncthreads();
        int pl = t & 31, og = t >> 5;
        float acc2[8];
        #pragma unroll
        for (int j = 0; j < 8; j++) acc2[j] = 0.f;
        #pragma unroll 4
        for (int c = 0; c < 64; c++){
            float xv = obuf[pl*65 + c];
            #pragma unroll
            for (int j = 0; j < 8; j++)
                acc2[j] = fmaf(__ldg(&g_c3wT[c*64 + og + 8*j]), xv, acc2[j]);
        }
        #pragma unroll
        for (int j = 0; j < 8; j++){
            int o2 = og + 8*j;
            dout[(size_t)b*262144 + (size_t)o2*4096 + l0 + pl] = acc2[j] + __ldg(c3b + o2);
        }
    }
}

extern "C" void kernel_launch(void* const* d_in, const int* in_sizes, int n_in,
                              void* d_out, int out_size){
    (void)in_sizes; (void)n_in;
    const float* rgb  = (const float*)d_in[0];
    const float* dte  = (const float*)d_in[1];
    const float* c1w  = (const float*)d_in[2];
    const float* c1b  = (const float*)d_in[3];
    const float* c2w  = (const float*)d_in[4];
    const float* c2b  = (const float*)d_in[5];
    const float* c3w  = (const float*)d_in[6];
    const float* c3b  = (const float*)d_in[7];
    const float* nw   = (const float*)d_in[8];
    const float* ipw  = (const float*)d_in[9];
    const float* cdw  = (const float*)d_in[10];
    const float* cdb  = (const float*)d_in[11];
    const float* xpw  = (const float*)d_in[12];
    const float* dtw  = (const float*)d_in[13];
    const float* dtb  = (const float*)d_in[14];
    const float* alog = (const float*)d_in[15];
    const float* Dp   = (const float*)d_in[16];
    const float* opw  = (const float*)d_in[17];
    float* out = (float*)d_out;

    cudaFuncSetAttribute(kFused, cudaFuncAttributeMaxDynamicSharedMemorySize, F_SMEM);

    kPrep<<<64, 256>>>(ipw, xpw, dtw, opw, alog, c3w);
    kConvIn<<<NCTA, NTH>>>(rgb, c1w, c1b, 0);
    kConvIn<<<NCTA, NTH>>>(dte, c2w, c2b, 1);

    // second output (final h) appended after conv output, if the harness expects it
    float* hExt = (out_size >= OUT_CONV + NPOS*DI*DS) ? (out + OUT_CONV) : nullptr;

    for (int k = 0; k < 6; k++){
        int last = (k == 5);
        kFused<<<NCTA, NTH, F_SMEM>>>(k & 1, k > 0, nw, cdw, cdb, dtb, Dp, c3b,
                                      (k == 0) ? 1 : 0, last, out,
                                      last ? hExt : nullptr);
    }
}